// round 11
// baseline (speedup 1.0000x reference)
#include <cuda_runtime.h>
#include <cuda_bf16.h>
#include <math.h>
#include <stdint.h>

typedef unsigned long long ull;
typedef unsigned int uint;

// Problem constants
#define SEQ   256
#define BSZ   16
#define HID   512
#define EMB   768
#define VOC   30522
#define TM1   99

// ---------------- scratch (device globals; no allocations) ----------------
__device__ float g_gi_f[SEQ*BSZ*1536];
__device__ float g_gi_b[SEQ*BSZ*1536];
__device__ float g_enc_out[BSZ*SEQ*1024];
__device__ float g_he[2][2][8192];         // encoder h double-buffer [parity][dir]
__device__ float g_hdd[2][8192];           // decoder h double-buffer [parity]
__device__ float g_v[1024];
__device__ float g_c0;
__device__ float g_ctx2h[BSZ*1024];
__device__ float g_ctx[BSZ*HID];
__device__ float g_ctxgi[BSZ*1536];
__device__ float g_gid[TM1*BSZ*1536];
__device__ float g_Hs[TM1*BSZ*HID];
__device__ float g_base[BSZ*VOC];
__device__ unsigned int g_cnt[4 * 32];
__device__ unsigned int g_flag[4 * 32];

// bf16-split buffers: A=[hi,lo,hi] along K, W=[hi,hi,lo] -> one GEMM over 3K
__device__ __nv_bfloat16 g_Ab_enc[4096 * 2304];
__device__ __nv_bfloat16 g_Ab_dec[1584 * 2304];
__device__ __nv_bfloat16 g_Ab_hs [1584 * 1536];
__device__ __nv_bfloat16 g_Wb_f  [1536 * 2304];
__device__ __nv_bfloat16 g_Wb_b  [1536 * 2304];
__device__ __nv_bfloat16 g_Wb_d  [1536 * 2304];
__device__ __nv_bfloat16 g_Wb_o  [(size_t)VOC * 1536];

// ---------------- f32x2 helpers -------------------------------------------
__device__ __forceinline__ ull fma2(ull a, ull b, ull c) {
    ull d;
    asm("fma.rn.f32x2 %0, %1, %2, %3;" : "=l"(d) : "l"(a), "l"(b), "l"(c));
    return d;
}
__device__ __forceinline__ ull add2(ull a, ull b) {
    ull d;
    asm("add.rn.f32x2 %0, %1, %2;" : "=l"(d) : "l"(a), "l"(b));
    return d;
}
__device__ __forceinline__ float hsum2(ull v) {
    float x, y;
    asm("mov.b64 {%0, %1}, %2;" : "=f"(x), "=f"(y) : "l"(v));
    return x + y;
}
union F4U { float4 f; ull u[2]; };

__device__ __forceinline__ float sigmoidf_(float x) { return 1.0f / (1.0f + expf(-x)); }

__device__ __forceinline__ uint smem_u32(const void* p) {
    uint a;
    asm("{ .reg .u64 t; cvta.to.shared.u64 t, %1; cvt.u32.u64 %0, t; }" : "=r"(a) : "l"(p));
    return a;
}

// ---------------- barrier: release-RMW arrival (no explicit threadfence) ---
__device__ __forceinline__ void gbar2(int id, unsigned nb, unsigned tgt) {
    __syncthreads();
    if (threadIdx.x == 0) {
        unsigned v;
        asm volatile("atom.release.gpu.add.u32 %0, [%1], %2;"
                     : "=r"(v) : "l"(&g_cnt[id * 32]), "r"(1u) : "memory");
        v += 1u;
        if (v == nb * tgt) {
            asm volatile("st.release.gpu.u32 [%0], %1;"
                         :: "l"(&g_flag[id * 32]), "r"(tgt) : "memory");
        } else {
            unsigned f;
            do {
                asm volatile("ld.acquire.gpu.u32 %0, [%1];"
                             : "=r"(f) : "l"(&g_flag[id * 32]) : "memory");
            } while (f < tgt);
        }
    }
    __syncthreads();
}

// ---------------- fold attention + barrier reset ---------------------------
__global__ void fold_kernel(const float* __restrict__ attn_W, const float* __restrict__ attn_b,
                            const float* __restrict__ comb_W, const float* __restrict__ comb_b) {
    if (blockIdx.x == 0 && threadIdx.x < 4) {
        g_cnt[threadIdx.x * 32] = 0u;
        g_flag[threadIdx.x * 32] = 0u;
    }
    int k = blockIdx.x * 256 + threadIdx.x;
    if (k < 1024) {
        float acc = 0.f;
        for (int j = 0; j < 512; j++) acc += comb_W[j] * attn_W[(size_t)j * 1536 + k];
        g_v[k] = acc;
    }
    if (blockIdx.x == 0 && threadIdx.x == 0) {
        float c = comb_b[0];
        for (int j = 0; j < 512; j++) c += comb_W[j] * attn_b[j];
        g_c0 = c;
    }
}

// ---------------- bf16 split conversion kernels ----------------------------
// W[n][koff+k] (ldw row stride) -> out[N][3K] = [hi, hi, lo]
__global__ void splitW(const float* __restrict__ W, int N, int K, int ldw, int koff,
                       __nv_bfloat16* __restrict__ out) {
    int idx = blockIdx.x * 256 + threadIdx.x;
    if (idx >= N * K) return;
    int n = idx / K, k = idx - n * K;
    float x = W[(size_t)n * ldw + koff + k];
    __nv_bfloat16 hi = __float2bfloat16(x);
    __nv_bfloat16 lo = __float2bfloat16(x - __bfloat162float(hi));
    size_t base = (size_t)n * 3 * K;
    out[base + k] = hi;
    out[base + K + k] = hi;
    out[base + 2 * K + k] = lo;
}

// A -> out[M][3K] = [hi, lo, hi]
__global__ void splitA_bert(const float* __restrict__ bert, __nv_bfloat16* __restrict__ out) {
    int idx = blockIdx.x * 256 + threadIdx.x;   // < 4096*768
    int m = idx / 768, k = idx - m * 768;
    int s = m >> 4, b = m & 15;
    float x = bert[((size_t)b * SEQ + s) * EMB + k];
    __nv_bfloat16 hi = __float2bfloat16(x);
    __nv_bfloat16 lo = __float2bfloat16(x - __bfloat162float(hi));
    size_t base = (size_t)m * 2304;
    out[base + k] = hi;
    out[base + 768 + k] = lo;
    out[base + 1536 + k] = hi;
}

__global__ void splitA_emb(const float* __restrict__ emb, const int* __restrict__ ids,
                           __nv_bfloat16* __restrict__ out) {
    int idx = blockIdx.x * 256 + threadIdx.x;   // < 1584*768
    int m = idx / 768, k = idx - m * 768;
    int t = m >> 4, b = m & 15;
    int tok = ids[b * 100 + t];
    float x = emb[(size_t)tok * EMB + k];
    __nv_bfloat16 hi = __float2bfloat16(x);
    __nv_bfloat16 lo = __float2bfloat16(x - __bfloat162float(hi));
    size_t base = (size_t)m * 2304;
    out[base + k] = hi;
    out[base + 768 + k] = lo;
    out[base + 1536 + k] = hi;
}

__global__ void splitA_hs(__nv_bfloat16* __restrict__ out) {
    int idx = blockIdx.x * 256 + threadIdx.x;   // < 1584*512
    int m = idx / 512, k = idx - m * 512;
    float x = g_Hs[(size_t)m * 512 + k];
    __nv_bfloat16 hi = __float2bfloat16(x);
    __nv_bfloat16 lo = __float2bfloat16(x - __bfloat162float(hi));
    size_t base = (size_t)m * 1536;
    out[base + k] = hi;
    out[base + 512 + k] = lo;
    out[base + 1024 + k] = hi;
}

// ---------------- tensor-core bf16 GEMM: C = A[M,K3] @ W[N,K3]^T -----------
__device__ __forceinline__ void ldsm_x4(uint* r, uint addr) {
    asm volatile("ldmatrix.sync.aligned.m8n8.x4.shared.b16 {%0,%1,%2,%3}, [%4];"
                 : "=r"(r[0]), "=r"(r[1]), "=r"(r[2]), "=r"(r[3]) : "r"(addr));
}
__device__ __forceinline__ void ldsm_x2(uint* r, uint addr) {
    asm volatile("ldmatrix.sync.aligned.m8n8.x2.shared.b16 {%0,%1}, [%2];"
                 : "=r"(r[0]), "=r"(r[1]) : "r"(addr));
}
__device__ __forceinline__ void mma16816(float* d, const uint* a, const uint* b) {
    asm volatile("mma.sync.aligned.m16n8k16.row.col.f32.bf16.bf16.f32 "
                 "{%0,%1,%2,%3}, {%4,%5,%6,%7}, {%8,%9}, {%0,%1,%2,%3};"
                 : "+f"(d[0]), "+f"(d[1]), "+f"(d[2]), "+f"(d[3])
                 : "r"(a[0]), "r"(a[1]), "r"(a[2]), "r"(a[3]), "r"(b[0]), "r"(b[1]));
}

// MODE 0: C -> g_gi_f / g_gi_b (sel), + bias[n]
// MODE 1: C -> g_gid, + g_ctxgi[b][n]
// MODE 2: C -> out[(b*99+t)*VOC + n], + g_base[b][n]
template<int MODE>
__global__ void __launch_bounds__(256, 2) bgemm(
    const __nv_bfloat16* __restrict__ A, const __nv_bfloat16* __restrict__ B,
    const float* __restrict__ bias, float* __restrict__ Cout,
    int sel, int M, int N, int K3)
{
    const int BM = 128, BN = 128, LDS = 40;
    __shared__ __nv_bfloat16 As[BM * LDS];
    __shared__ __nv_bfloat16 Bs[BN * LDS];

    int tid = threadIdx.x, lane = tid & 31, warp = tid >> 5;
    int warp_m = warp >> 2, warp_n = warp & 3;
    int row0 = blockIdx.y * BM, col0 = blockIdx.x * BN;

    // global->smem mapping: thread loads row lr, 32B half lh (2x uint4)
    int lr = tid >> 1, lh = tid & 1;
    const __nv_bfloat16* Ap = (row0 + lr < M) ? (A + (size_t)(row0 + lr) * K3 + lh * 16) : nullptr;
    const __nv_bfloat16* Bp = (col0 + lr < N) ? (B + (size_t)(col0 + lr) * K3 + lh * 16) : nullptr;
    __nv_bfloat16* Asw = As + lr * LDS + lh * 16;
    __nv_bfloat16* Bsw = Bs + lr * LDS + lh * 16;

    uint As_u = smem_u32(As);
    uint Bs_u = smem_u32(Bs);

    float acc[4][4][4];
    #pragma unroll
    for (int mi = 0; mi < 4; mi++)
        #pragma unroll
        for (int ni = 0; ni < 4; ni++)
            #pragma unroll
            for (int e = 0; e < 4; e++) acc[mi][ni][e] = 0.f;

    uint4 pa0, pa1, pb0, pb1;
    const uint4 z4 = make_uint4(0, 0, 0, 0);
    pa0 = Ap ? *(const uint4*)(Ap) : z4;
    pa1 = Ap ? *(const uint4*)(Ap + 8) : z4;
    pb0 = Bp ? *(const uint4*)(Bp) : z4;
    pb1 = Bp ? *(const uint4*)(Bp + 8) : z4;

    int T = K3 / 32;
    for (int kt = 0; kt < T; kt++) {
        __syncthreads();
        *(uint4*)(Asw) = pa0;  *(uint4*)(Asw + 8) = pa1;
        *(uint4*)(Bsw) = pb0;  *(uint4*)(Bsw + 8) = pb1;
        __syncthreads();
        if (kt + 1 < T) {
            int ko = (kt + 1) * 32;
            pa0 = Ap ? *(const uint4*)(Ap + ko) : z4;
            pa1 = Ap ? *(const uint4*)(Ap + ko + 8) : z4;
            pb0 = Bp ? *(const uint4*)(Bp + ko) : z4;
            pb1 = Bp ? *(const uint4*)(Bp + ko + 8) : z4;
        }
        #pragma unroll
        for (int kc = 0; kc < 2; kc++) {
            uint af[4][4], bfr[4][2];
            #pragma unroll
            for (int mi = 0; mi < 4; mi++) {
                uint a = As_u + (((warp_m * 64 + mi * 16 + (lane & 15)) * LDS
                                 + kc * 16 + (lane >> 4) * 8) << 1);
                ldsm_x4(af[mi], a);
            }
            #pragma unroll
            for (int ni = 0; ni < 4; ni++) {
                uint a = Bs_u + (((warp_n * 32 + ni * 8 + (lane & 7)) * LDS
                                 + kc * 16 + ((lane >> 3) & 1) * 8) << 1);
                ldsm_x2(bfr[ni], a);
            }
            #pragma unroll
            for (int mi = 0; mi < 4; mi++)
                #pragma unroll
                for (int ni = 0; ni < 4; ni++)
                    mma16816(acc[mi][ni], af[mi], bfr[ni]);
        }
    }

    // epilogue
    int gid = lane >> 2, tg = lane & 3;
    #pragma unroll
    for (int mi = 0; mi < 4; mi++) {
        #pragma unroll
        for (int ni = 0; ni < 4; ni++) {
            #pragma unroll
            for (int e = 0; e < 4; e++) {
                int m = row0 + warp_m * 64 + mi * 16 + gid + (e >> 1) * 8;
                int n = col0 + warp_n * 32 + ni * 8 + tg * 2 + (e & 1);
                if (m >= M || n >= N) continue;
                float val = acc[mi][ni][e];
                int b = m & 15, t = m >> 4;
                if (MODE == 0) {
                    val += bias[n];
                    float* dst = sel ? g_gi_b : g_gi_f;
                    dst[(size_t)m * 1536 + n] = val;
                } else if (MODE == 1) {
                    val += g_ctxgi[b * 1536 + n];
                    g_gid[(size_t)m * 1536 + n] = val;
                } else {
                    val += g_base[(size_t)b * VOC + n];
                    Cout[((size_t)b * TM1 + t) * VOC + n] = val;
                }
            }
        }
    }
}

// ---------------- persistent GRU scan core ---------------------------------
struct ScanSmem {
    float Wsm[12 * 512];
    float hs[8192];
    float red[12 * 2 * 16];
};

template<int NSTEPS, int DIRS>
__device__ __forceinline__ void scan_core(
    const float* __restrict__ Whh, const float* __restrict__ bhh,
    const float* __restrict__ gi,
    float* __restrict__ buf0, float* __restrict__ buf1,
    const float* __restrict__ init_a, const float* __restrict__ init_b,
    int dir, int i0, int bar_id, unsigned nb,
    float* __restrict__ extra_out)
{
    extern __shared__ char smraw[];
    ScanSmem* S = (ScanSmem*)smraw;

    int tid = threadIdx.x;
    int warp = tid >> 5, lane = tid & 31;
    int i_local = warp & 3, ks_hi = warp >> 2;
    int b = lane & 15, ks_lo = lane >> 4;
    int k0 = (ks_hi * 2 + ks_lo) * 128;

    for (int x = tid; x < 1536; x += 256) {
        int r = x >> 7;
        int c = (x & 127) * 4;
        int g = r >> 2, i_l = r & 3;
        *(float4*)(S->Wsm + r * 512 + c) =
            __ldg((const float4*)(Whh + ((size_t)(g * 512) + i0 + i_l) * 512 + c));
    }
    if (init_a == nullptr) {
        for (int x = tid; x < 2048; x += 256)
            ((float4*)S->hs)[x] = make_float4(0.f, 0.f, 0.f, 0.f);
    } else {
        for (int x = tid; x < 2048; x += 256) {
            float4 a = __ldcg(((const float4*)init_a) + x);
            float4 c = __ldcg(((const float4*)init_b) + x);
            ((float4*)S->hs)[x] = make_float4(a.x + c.x, a.y + c.y, a.z + c.z, a.w + c.w);
        }
    }
    __syncthreads();

    const float* wr = S->Wsm + (0 * 4 + i_local) * 512 + k0;
    const float* wz = S->Wsm + (1 * 4 + i_local) * 512 + k0;
    const float* wn = S->Wsm + (2 * 4 + i_local) * 512 + k0;
    const float* hbase = S->hs + (k0 >> 2) * 64 + b * 4;

    int b2 = tid & 15, il2 = (tid >> 4) & 3;
    int i = i0 + il2;
    float bh_r = bhh[i], bh_z = bhh[i + 512], bh_n = bhh[i + 1024];
    int hidx = (i >> 2) * 64 + b2 * 4 + (i & 3);

    for (int step = 0; step < NSTEPS; step++) {
        int s = (DIRS == 2 && dir) ? (NSTEPS - 1 - step) : step;
        float* wbuf = (step & 1) ? buf0 : buf1;

        float gv0 = 0.f, gv1 = 0.f, gv2 = 0.f;
        if (tid < 64) {
            const float* gp = gi + ((size_t)s * 16 + b2) * 1536 + i;
            gv0 = __ldg(gp);
            gv1 = __ldg(gp + 512);
            gv2 = __ldg(gp + 1024);
        }

        ull pr = 0ull, pz = 0ull, pn = 0ull;
        #pragma unroll 8
        for (int kq = 0; kq < 32; kq++) {
            F4U h4; h4.f = *(const float4*)(hbase + kq * 64);
            F4U w;
            w.f = *(const float4*)(wr + kq * 4);
            pr = fma2(w.u[0], h4.u[0], pr); pr = fma2(w.u[1], h4.u[1], pr);
            w.f = *(const float4*)(wz + kq * 4);
            pz = fma2(w.u[0], h4.u[0], pz); pz = fma2(w.u[1], h4.u[1], pz);
            w.f = *(const float4*)(wn + kq * 4);
            pn = fma2(w.u[0], h4.u[0], pn); pn = fma2(w.u[1], h4.u[1], pn);
        }
        pr = add2(pr, __shfl_xor_sync(0xffffffffu, pr, 16));
        pz = add2(pz, __shfl_xor_sync(0xffffffffu, pz, 16));
        pn = add2(pn, __shfl_xor_sync(0xffffffffu, pn, 16));
        if (ks_lo == 0) {
            S->red[(0 * 4 + i_local) * 32 + ks_hi * 16 + b] = hsum2(pr);
            S->red[(1 * 4 + i_local) * 32 + ks_hi * 16 + b] = hsum2(pz);
            S->red[(2 * 4 + i_local) * 32 + ks_hi * 16 + b] = hsum2(pn);
        }
        __syncthreads();

        if (tid < 64) {
            float dr = S->red[(0 * 4 + il2) * 32 + b2] + S->red[(0 * 4 + il2) * 32 + 16 + b2];
            float dz = S->red[(1 * 4 + il2) * 32 + b2] + S->red[(1 * 4 + il2) * 32 + 16 + b2];
            float dn = S->red[(2 * 4 + il2) * 32 + b2] + S->red[(2 * 4 + il2) * 32 + 16 + b2];
            float r = sigmoidf_(gv0 + dr + bh_r);
            float z = sigmoidf_(gv1 + dz + bh_z);
            float n = tanhf(gv2 + r * (dn + bh_n));
            float hnew = (1.f - z) * n + z * S->hs[hidx];
            wbuf[hidx] = hnew;
            if (DIRS == 2)
                extra_out[((size_t)b2 * SEQ + s) * 1024 + dir * 512 + i] = hnew;
            else
                extra_out[((size_t)s * 16 + b2) * 512 + i] = hnew;
        }

        if (step + 1 < NSTEPS) {
            gbar2(bar_id, nb, (unsigned)(step + 1));
            for (int x = tid; x < 2048; x += 256)
                ((float4*)S->hs)[x] = __ldcg(((const float4*)wbuf) + x);
            __syncthreads();
        }
    }
}

__global__ void __launch_bounds__(256, 2) enc_scan4(
    const float* __restrict__ Whh_f, const float* __restrict__ bhh_f,
    const float* __restrict__ Whh_b, const float* __restrict__ bhh_b)
{
    int dir = blockIdx.x >> 7;
    int blk = blockIdx.x & 127;
    scan_core<SEQ, 2>(dir ? Whh_b : Whh_f, dir ? bhh_b : bhh_f,
                      dir ? g_gi_b : g_gi_f,
                      g_he[0][dir], g_he[1][dir],
                      nullptr, nullptr,
                      dir, blk * 4, dir, 128, g_enc_out);
}

__global__ void __launch_bounds__(256, 2) dec_scan4(const float* __restrict__ Whh,
                                                    const float* __restrict__ bhh)
{
    scan_core<TM1, 1>(Whh, bhh, g_gid,
                      g_hdd[0], g_hdd[1],
                      g_he[0][0], g_he[0][1],
                      0, blockIdx.x * 4, 2, 128, g_Hs);
}

// ---------------- attention: scores + softmax + ctx2h (once) ---------------
__global__ void attn_kernel(const int* __restrict__ amask) {
    int b = blockIdx.x, tid = threadIdx.x;
    __shared__ float vs[1024];
    __shared__ float ws[SEQ];
    __shared__ float red[16];
    for (int x = tid; x < 1024; x += 256) vs[x] = g_v[x];
    __syncthreads();

    const float* row = g_enc_out + ((size_t)b * SEQ + tid) * 1024;
    ull acc2 = 0ull;
    for (int k = 0; k < 1024; k += 4) {
        F4U e, v;
        e.f = *(const float4*)(row + k);
        v.f = *(const float4*)(vs + k);
        acc2 = fma2(e.u[0], v.u[0], acc2);
        acc2 = fma2(e.u[1], v.u[1], acc2);
    }
    float sc = hsum2(acc2) + g_c0;
    if (amask[b * SEQ + tid] == 0) sc = -1e9f;

    float m = sc;
    #pragma unroll
    for (int o = 16; o; o >>= 1) m = fmaxf(m, __shfl_xor_sync(0xffffffffu, m, o));
    if ((tid & 31) == 0) red[tid >> 5] = m;
    __syncthreads();
    if (tid < 32) {
        float t = (tid < 8) ? red[tid] : -3.4e38f;
        #pragma unroll
        for (int o = 4; o; o >>= 1) t = fmaxf(t, __shfl_xor_sync(0xffffffffu, t, o));
        if (tid == 0) red[0] = t;
    }
    __syncthreads();
    float mx = red[0];
    float e = expf(sc - mx);
    float sm = e;
    #pragma unroll
    for (int o = 16; o; o >>= 1) sm += __shfl_xor_sync(0xffffffffu, sm, o);
    __syncthreads();
    if ((tid & 31) == 0) red[8 + (tid >> 5)] = sm;
    __syncthreads();
    if (tid < 32) {
        float t = (tid < 8) ? red[8 + tid] : 0.f;
        #pragma unroll
        for (int o = 4; o; o >>= 1) t += __shfl_xor_sync(0xffffffffu, t, o);
        if (tid == 0) red[0] = t;
    }
    __syncthreads();
    float total = red[0];
    ws[tid] = e / total;
    __syncthreads();

    #pragma unroll
    for (int kk = 0; kk < 4; kk++) {
        int k = tid + kk * 256;
        float a2 = 0.f;
        for (int s = 0; s < SEQ; s++)
            a2 += ws[s] * g_enc_out[((size_t)b * SEQ + s) * 1024 + k];
        g_ctx2h[b * 1024 + k] = a2;
    }
}

// ---------------- small GEMMs: proj / ctx_gi / base ------------------------
__global__ void small_mm(const float* __restrict__ W, const float* __restrict__ bias,
                         int mode, int N, int K, int ldw, int koff) {
    int idx = blockIdx.x * 256 + threadIdx.x;
    if (idx >= 16 * N) return;
    int b = idx & 15, n = idx >> 4;
    const float* A = (mode == 0) ? (g_ctx2h + b * 1024) : (g_ctx + b * 512);
    const float* w = W + (size_t)n * ldw + koff;
    ull acc2 = 0ull;
    for (int k = 0; k < K; k += 4) {
        F4U av, wv;
        av.f = *(const float4*)(A + k);
        wv.f = *(const float4*)(w + k);
        acc2 = fma2(av.u[0], wv.u[0], acc2);
        acc2 = fma2(av.u[1], wv.u[1], acc2);
    }
    float acc = hsum2(acc2) + bias[n];
    if (mode == 0)      g_ctx[b * 512 + n] = acc;
    else if (mode == 1) g_ctxgi[b * 1536 + n] = acc;
    else                g_base[(size_t)b * VOC + n] = acc;
}

// ---------------- launch -------------------------------------------------
extern "C" void kernel_launch(void* const* d_in, const int* in_sizes, int n_in,
                              void* d_out, int out_size) {
    const float* bert   = (const float*)d_in[0];
    const int*   amask  = (const int*)d_in[1];
    const int*   ids    = (const int*)d_in[2];
    const float* emb    = (const float*)d_in[3];
    const float* eWih_f = (const float*)d_in[4];
    const float* eWhh_f = (const float*)d_in[5];
    const float* ebih_f = (const float*)d_in[6];
    const float* ebhh_f = (const float*)d_in[7];
    const float* eWih_b = (const float*)d_in[8];
    const float* eWhh_b = (const float*)d_in[9];
    const float* ebih_b = (const float*)d_in[10];
    const float* ebhh_b = (const float*)d_in[11];
    const float* dWih   = (const float*)d_in[12];
    const float* dWhh   = (const float*)d_in[13];
    const float* dbih   = (const float*)d_in[14];
    const float* dbhh   = (const float*)d_in[15];
    const float* attn_W = (const float*)d_in[16];
    const float* attn_b = (const float*)d_in[17];
    const float* comb_W = (const float*)d_in[18];
    const float* comb_b = (const float*)d_in[19];
    const float* proj_W = (const float*)d_in[20];
    const float* proj_b = (const float*)d_in[21];
    const float* out_W  = (const float*)d_in[22];
    const float* out_b  = (const float*)d_in[23];
    float* out = (float*)d_out;

    const int SCAN_SMEM = (int)sizeof(ScanSmem);

    static int attr_done = 0;
    if (!attr_done) {
        cudaFuncSetAttribute(enc_scan4, cudaFuncAttributeMaxDynamicSharedMemorySize, SCAN_SMEM);
        cudaFuncSetAttribute(dec_scan4, cudaFuncAttributeMaxDynamicSharedMemorySize, SCAN_SMEM);
        attr_done = 1;
    }

    // attention folding + barrier reset
    fold_kernel<<<4, 256>>>(attn_W, attn_b, comb_W, comb_b);

    // bf16 splits (weights + bert)
    splitW<<<(1536 * 768 + 255) / 256, 256>>>(eWih_f, 1536, 768, 768, 0, g_Wb_f);
    splitW<<<(1536 * 768 + 255) / 256, 256>>>(eWih_b, 1536, 768, 768, 0, g_Wb_b);
    splitW<<<(1536 * 768 + 255) / 256, 256>>>(dWih, 1536, 768, 1280, 0, g_Wb_d);
    splitW<<<(VOC * 512 + 255) / 256, 256>>>(out_W, VOC, 512, 1024, 0, g_Wb_o);
    splitA_bert<<<(4096 * 768) / 256, 256>>>(bert, g_Ab_enc);

    // encoder input gates (tensor cores)
    bgemm<0><<<dim3(12, 32), 256>>>(g_Ab_enc, g_Wb_f, ebih_f, nullptr, 0, 4096, 1536, 2304);
    bgemm<0><<<dim3(12, 32), 256>>>(g_Ab_enc, g_Wb_b, ebih_b, nullptr, 1, 4096, 1536, 2304);

    // bidirectional encoder scan
    enc_scan4<<<256, 256, SCAN_SMEM>>>(eWhh_f, ebhh_f, eWhh_b, ebhh_b);

    // attention (once)
    attn_kernel<<<16, 256>>>(amask);

    // ctx = ctx2h @ proj_W.T + proj_b ; ctx_gi = ctx @ dec_Wih[:,768:].T + dec_bih
    small_mm<<<32, 256>>>(proj_W, proj_b, 0, 512, 1024, 1024, 0);
    small_mm<<<96, 256>>>(dWih, dbih, 1, 1536, 512, 1280, 768);

    // decoder input gates (tensor cores, gathered emb)
    splitA_emb<<<(1584 * 768) / 256, 256>>>(emb, ids, g_Ab_dec);
    bgemm<1><<<dim3(12, 13), 256>>>(g_Ab_dec, g_Wb_d, nullptr, nullptr, 0, 1584, 1536, 2304);

    // decoder scan
    dec_scan4<<<128, 256, SCAN_SMEM>>>(dWhh, dbhh);

    // base = ctx @ out_W[:,512:].T + out_b
    small_mm<<<1908, 256>>>(out_W, out_b, 2, VOC, 512, 1024, 512);

    // logits = Hs @ out_W[:,:512].T + base (tensor cores)
    splitA_hs<<<(1584 * 512) / 256, 256>>>(g_Ab_hs);
    bgemm<2><<<dim3(239, 13), 256>>>(g_Ab_hs, g_Wb_o, nullptr, out, 0, 1584, VOC, 1536);
}

// round 15
// speedup vs baseline: 3.2636x; 3.2636x over previous
#include <cuda_runtime.h>
#include <math.h>
#include <stdint.h>

typedef unsigned long long ull;
typedef unsigned int uint;

// Problem constants
#define SEQ   256
#define BSZ   16
#define HID   512
#define EMB   768
#define VOC   30522
#define TM1   99

// ---------------- scratch (device globals; no allocations) ----------------
__device__ float g_gi_f[SEQ*BSZ*1536];
__device__ float g_gi_b[SEQ*BSZ*1536];
__device__ float g_enc_out[BSZ*SEQ*1024];
__device__ float g_he[2][2][8192];     // [parity][dir], layout [b*512 + k]
__device__ float g_hdd[2][8192];       // [parity], layout [b*512 + k]
__device__ float g_v[1024];
__device__ float g_c0;
__device__ float g_ctx2h[BSZ*1024];
__device__ float g_ctx[BSZ*HID];
__device__ float g_ctxgi[BSZ*1536];
__device__ float g_gid[TM1*BSZ*1536];
__device__ float g_Hs[TM1*BSZ*HID];
__device__ float g_base[BSZ*VOC];
__device__ unsigned int g_cnt[4 * 32];
__device__ unsigned int g_flag[4 * 32];

// ---------------- f32x2 helpers -------------------------------------------
__device__ __forceinline__ ull fma2(ull a, ull b, ull c) {
    ull d;
    asm("fma.rn.f32x2 %0, %1, %2, %3;" : "=l"(d) : "l"(a), "l"(b), "l"(c));
    return d;
}
__device__ __forceinline__ ull add2(ull a, ull b) {
    ull d;
    asm("add.rn.f32x2 %0, %1, %2;" : "=l"(d) : "l"(a), "l"(b));
    return d;
}
__device__ __forceinline__ ull dup2(float x) {
    ull d;
    asm("mov.b64 %0, {%1, %1};" : "=l"(d) : "f"(x));
    return d;
}
__device__ __forceinline__ float hsum2(ull v) {
    float x, y;
    asm("mov.b64 {%0, %1}, %2;" : "=f"(x), "=f"(y) : "l"(v));
    return x + y;
}
__device__ __forceinline__ float2 unp2(ull v) {
    float2 r;
    asm("mov.b64 {%0, %1}, %2;" : "=f"(r.x), "=f"(r.y) : "l"(v));
    return r;
}
union F4U { float4 f; ull u[2]; };

__device__ __forceinline__ float sigmoidf_(float x) { return 1.0f / (1.0f + expf(-x)); }

// ---------------- grid barrier (split count/flag) --------------------------
__device__ __forceinline__ void gbar2(int id, unsigned nb, unsigned tgt) {
    __syncthreads();
    if (threadIdx.x == 0) {
        unsigned v;
        asm volatile("atom.release.gpu.add.u32 %0, [%1], %2;"
                     : "=r"(v) : "l"(&g_cnt[id * 32]), "r"(1u) : "memory");
        v += 1u;
        if (v == nb * tgt) {
            asm volatile("st.release.gpu.u32 [%0], %1;"
                         :: "l"(&g_flag[id * 32]), "r"(tgt) : "memory");
        } else {
            unsigned f;
            do {
                asm volatile("ld.acquire.gpu.u32 %0, [%1];"
                             : "=r"(f) : "l"(&g_flag[id * 32]) : "memory");
            } while (f < tgt);
        }
    }
    __syncthreads();
}

// ---------------- fold attention + barrier reset ---------------------------
__global__ void fold_kernel(const float* __restrict__ attn_W, const float* __restrict__ attn_b,
                            const float* __restrict__ comb_W, const float* __restrict__ comb_b) {
    if (blockIdx.x == 0 && threadIdx.x < 4) {
        g_cnt[threadIdx.x * 32] = 0u;
        g_flag[threadIdx.x * 32] = 0u;
    }
    int k = blockIdx.x * 256 + threadIdx.x;
    if (k < 1024) {
        float acc = 0.f;
        for (int j = 0; j < 512; j++) acc += comb_W[j] * attn_W[(size_t)j * 1536 + k];
        g_v[k] = acc;
    }
    if (blockIdx.x == 0 && threadIdx.x == 0) {
        float c = comb_b[0];
        for (int j = 0; j < 512; j++) c += comb_W[j] * attn_b[j];
        g_c0 = c;
    }
}

// ---------------- 128x128x32 SGEMM with f32x2 FFMA2: C = A @ W.T -----------
// MODE 0: C -> g_gi_f / g_gi_b (sel), + bias[n]
// MODE 1: A rows gathered from emb, C -> g_gid, + g_ctxgi[b][n]
// MODE 2: A = g_Hs, C -> out[(b*99+t)*VOC + n], + g_base[b][n]
template<int MODE>
__global__ void __launch_bounds__(256) sgemm2(
    const float* __restrict__ Asrc, const float* __restrict__ W, int ldw,
    const float* __restrict__ bias, const int* __restrict__ toks,
    float* __restrict__ Cout, int sel, int M, int N, int K)
{
    const int BM = 128, BN = 128, BK = 32;
    extern __shared__ char smraw[];
    float* As = (float*)smraw;
    ull*   Bs = (ull*)(smraw + BK * BM * 4);

    int tid = threadIdx.x;
    int row0 = blockIdx.y * BM, col0 = blockIdx.x * BN;
    int tx = tid & 15, ty = tid >> 4;

    int a_m  = tid >> 1;
    int a_kq = (tid & 1) * 16;
    int am = row0 + a_m;
    const float* Ap = nullptr;
    if (am < M) {
        if (MODE == 0) {
            int s = am >> 4, b = am & 15;
            Ap = Asrc + ((size_t)b * SEQ + s) * EMB;
        } else if (MODE == 1) {
            int t = am >> 4, b = am & 15;
            Ap = Asrc + (size_t)toks[b * 100 + t] * EMB;
        } else {
            Ap = g_Hs + (size_t)am * HID;
        }
    }
    int b_n  = tid >> 1;
    int b_kq = (tid & 1) * 16;
    int wn = col0 + b_n;
    const float* Wp = (wn < N) ? (W + (size_t)wn * ldw) : nullptr;

    ull acc[4][8];
    #pragma unroll
    for (int ip = 0; ip < 4; ip++)
        #pragma unroll
        for (int j = 0; j < 8; j++) acc[ip][j] = 0ull;

    float4 rA[4], rB[4];
    #pragma unroll
    for (int q = 0; q < 4; q++) {
        rA[q] = Ap ? *(const float4*)(Ap + a_kq + q * 4) : make_float4(0.f, 0.f, 0.f, 0.f);
        rB[q] = Wp ? *(const float4*)(Wp + b_kq + q * 4) : make_float4(0.f, 0.f, 0.f, 0.f);
    }

    int T = K / BK;
    for (int t = 0; t < T; t++) {
        __syncthreads();
        #pragma unroll
        for (int q = 0; q < 4; q++) {
            int ka = a_kq + q * 4;
            As[(ka + 0) * BM + a_m] = rA[q].x;
            As[(ka + 1) * BM + a_m] = rA[q].y;
            As[(ka + 2) * BM + a_m] = rA[q].z;
            As[(ka + 3) * BM + a_m] = rA[q].w;
            int kb = b_kq + q * 4;
            Bs[(kb + 0) * BN + b_n] = dup2(rB[q].x);
            Bs[(kb + 1) * BN + b_n] = dup2(rB[q].y);
            Bs[(kb + 2) * BN + b_n] = dup2(rB[q].z);
            Bs[(kb + 3) * BN + b_n] = dup2(rB[q].w);
        }
        __syncthreads();
        if (t + 1 < T) {
            int k0 = (t + 1) * BK;
            #pragma unroll
            for (int q = 0; q < 4; q++) {
                rA[q] = Ap ? *(const float4*)(Ap + k0 + a_kq + q * 4) : make_float4(0.f, 0.f, 0.f, 0.f);
                rB[q] = Wp ? *(const float4*)(Wp + k0 + b_kq + q * 4) : make_float4(0.f, 0.f, 0.f, 0.f);
            }
        }
        #pragma unroll 8
        for (int kk = 0; kk < BK; kk++) {
            F4U a0, a1;
            a0.f = *(const float4*)&As[kk * BM + ty * 8];
            a1.f = *(const float4*)&As[kk * BM + ty * 8 + 4];
            ull ap[4] = {a0.u[0], a0.u[1], a1.u[0], a1.u[1]};
            const ull* bp = Bs + kk * BN + tx * 8;
            ulonglong2 q0 = *(const ulonglong2*)(bp);
            ulonglong2 q1 = *(const ulonglong2*)(bp + 2);
            ulonglong2 q2 = *(const ulonglong2*)(bp + 4);
            ulonglong2 q3 = *(const ulonglong2*)(bp + 6);
            ull bb[8] = {q0.x, q0.y, q1.x, q1.y, q2.x, q2.y, q3.x, q3.y};
            #pragma unroll
            for (int ip = 0; ip < 4; ip++)
                #pragma unroll
                for (int j = 0; j < 8; j++)
                    acc[ip][j] = fma2(ap[ip], bb[j], acc[ip][j]);
        }
    }

    #pragma unroll
    for (int ip = 0; ip < 4; ip++) {
        int m0 = row0 + ty * 8 + ip * 2;
        #pragma unroll
        for (int j = 0; j < 8; j++) {
            int n = col0 + tx * 8 + j;
            if (n >= N) continue;
            float2 v = unp2(acc[ip][j]);
            #pragma unroll
            for (int h = 0; h < 2; h++) {
                int m = m0 + h;
                if (m >= M) continue;
                float val = (h == 0) ? v.x : v.y;
                int b = m & 15, t = m >> 4;
                if (MODE == 0) {
                    val += bias[n];
                    float* dst = sel ? g_gi_b : g_gi_f;
                    dst[(size_t)m * 1536 + n] = val;
                } else if (MODE == 1) {
                    val += g_ctxgi[b * 1536 + n];
                    g_gid[(size_t)m * 1536 + n] = val;
                } else {
                    val += g_base[(size_t)b * VOC + n];
                    Cout[((size_t)b * TM1 + t) * VOC + n] = val;
                }
            }
        }
    }
}

// ---------------- persistent GRU scan, v5: weight-reuse + swizzled h -------
// Block: 256 threads = 8 warps. warp = i (block covers 8 i).
// Lane: ks = lane>>2 (8 splits x 64 k), bg = lane&3 (4 b's each: b = bg*4+bb).
// smem: Wsm 24 rows (3 gates x 8 i) + hs 16 rows (b), both in padded layout
//   off(row,k) = row*548 + (k>>6)*68 + (k&63)   (bank-spread over ks)
// Per kq(4k): 3 w LDS.128 (8 distinct addrs/warp) + 4 h LDS.128 -> 24 FFMA2.
// Reduce over ks via shfl_xor(4,8,16); lanes with ks<4 finish gates for
// b = bg*4 + ks. h double-buffered in global [b*512+k].
#define SROW 548
#define SCAN5_SMEM ((24 + 16) * SROW * 4)

template<int NSTEPS, int DIRS>
__device__ __forceinline__ void scan_core5(
    const float* __restrict__ Whh, const float* __restrict__ bhh,
    const float* __restrict__ gi,
    float* __restrict__ buf0, float* __restrict__ buf1,
    const float* __restrict__ init_a, const float* __restrict__ init_b,
    int dir, int i0, int bar_id, unsigned nb,
    float* __restrict__ extra)
{
    extern __shared__ float sm5[];
    float* Wsm = sm5;               // 24*548
    float* hs  = sm5 + 24 * SROW;   // 16*548

    int tid = threadIdx.x, il = tid >> 5, lane = tid & 31;
    int ks = lane >> 2, bg = lane & 3;
    int i = i0 + il;

    // load weight slice: row r = g*8+il_  <-  Whh[g*512 + i0 + il_][:]
    for (int x = tid; x < 24 * 128; x += 256) {
        int r = x >> 7, c = (x & 127) * 4;
        int g = r >> 3, il_ = r & 7;
        float4 v = __ldg((const float4*)(Whh + ((size_t)(g * 512) + i0 + il_) * 512 + c));
        *(float4*)(Wsm + r * SROW + (c >> 6) * 68 + (c & 63)) = v;
    }
    // h init
    if (init_a == nullptr) {
        for (int x = tid; x < 16 * SROW; x += 256) hs[x] = 0.f;
    } else {
        for (int x = tid; x < 2048; x += 256) {
            int b = x >> 7, c = (x & 127) * 4;
            float4 a = __ldcg((const float4*)(init_a + b * 512 + c));
            float4 d = __ldcg((const float4*)(init_b + b * 512 + c));
            *(float4*)(hs + b * SROW + (c >> 6) * 68 + (c & 63)) =
                make_float4(a.x + d.x, a.y + d.y, a.z + d.z, a.w + d.w);
        }
    }
    __syncthreads();

    const float* wb0 = Wsm + il * SROW + ks * 68;
    const float* wb1 = wb0 + 8 * SROW;
    const float* wb2 = wb0 + 16 * SROW;
    const float* hb_ = hs + ks * 68;

    int bgate = bg * 4 + ks;                 // gate-lane's b (valid for ks<4)
    float bh_r = bhh[i], bh_z = bhh[i + 512], bh_n = bhh[i + 1024];
    int hpidx = (bgate < 16) ? (bgate * SROW + (i >> 6) * 68 + (i & 63)) : 0;

    for (int step = 0; step < NSTEPS; step++) {
        int s = (DIRS == 2 && dir) ? (NSTEPS - 1 - step) : step;
        float* wbuf = (step & 1) ? buf0 : buf1;

        float gv0 = 0.f, gv1 = 0.f, gv2 = 0.f;
        if (ks < 4) {
            const float* gp = gi + ((size_t)s * 16 + bgate) * 1536 + i;
            gv0 = __ldg(gp); gv1 = __ldg(gp + 512); gv2 = __ldg(gp + 1024);
        }

        ull acc[3][4];
        #pragma unroll
        for (int g = 0; g < 3; g++)
            #pragma unroll
            for (int bb = 0; bb < 4; bb++) acc[g][bb] = 0ull;

        #pragma unroll
        for (int kq = 0; kq < 16; kq++) {
            F4U w0, w1, w2;
            w0.f = *(const float4*)(wb0 + kq * 4);
            w1.f = *(const float4*)(wb1 + kq * 4);
            w2.f = *(const float4*)(wb2 + kq * 4);
            #pragma unroll
            for (int bb = 0; bb < 4; bb++) {
                F4U h4;
                h4.f = *(const float4*)(hb_ + (bg * 4 + bb) * SROW + kq * 4);
                acc[0][bb] = fma2(w0.u[0], h4.u[0], acc[0][bb]);
                acc[0][bb] = fma2(w0.u[1], h4.u[1], acc[0][bb]);
                acc[1][bb] = fma2(w1.u[0], h4.u[0], acc[1][bb]);
                acc[1][bb] = fma2(w1.u[1], h4.u[1], acc[1][bb]);
                acc[2][bb] = fma2(w2.u[0], h4.u[0], acc[2][bb]);
                acc[2][bb] = fma2(w2.u[1], h4.u[1], acc[2][bb]);
            }
        }

        // reduce over ks (lane bits 2,3,4)
        #pragma unroll
        for (int g = 0; g < 3; g++)
            #pragma unroll
            for (int bb = 0; bb < 4; bb++) {
                ull v = acc[g][bb];
                v = add2(v, __shfl_xor_sync(0xffffffffu, v, 4));
                v = add2(v, __shfl_xor_sync(0xffffffffu, v, 8));
                v = add2(v, __shfl_xor_sync(0xffffffffu, v, 16));
                acc[g][bb] = v;
            }

        if (ks < 4) {
            float dr = 0.f, dz = 0.f, dn = 0.f;
            #pragma unroll
            for (int q = 0; q < 4; q++) if (q == ks) {
                dr = hsum2(acc[0][q]);
                dz = hsum2(acc[1][q]);
                dn = hsum2(acc[2][q]);
            }
            float r = sigmoidf_(gv0 + dr + bh_r);
            float z = sigmoidf_(gv1 + dz + bh_z);
            float n = tanhf(gv2 + r * (dn + bh_n));
            float hprev = hs[hpidx];
            float hnew = (1.f - z) * n + z * hprev;
            wbuf[bgate * 512 + i] = hnew;
            if (DIRS == 2)
                extra[((size_t)bgate * SEQ + s) * 1024 + dir * 512 + i] = hnew;
            else
                extra[((size_t)s * 16 + bgate) * 512 + i] = hnew;
        }

        if (step + 1 < NSTEPS) {
            gbar2(bar_id, nb, (unsigned)(step + 1));
            for (int x = tid; x < 2048; x += 256) {
                int b = x >> 7, c = (x & 127) * 4;
                float4 v = __ldcg((const float4*)(wbuf + b * 512 + c));
                *(float4*)(hs + b * SROW + (c >> 6) * 68 + (c & 63)) = v;
            }
            __syncthreads();
        }
    }
}

// encoder: 128 blocks (64/dir, 8 i each)
__global__ void __launch_bounds__(256, 1) enc_scan5(
    const float* __restrict__ Whh_f, const float* __restrict__ bhh_f,
    const float* __restrict__ Whh_b, const float* __restrict__ bhh_b)
{
    int dir = blockIdx.x >> 6;
    int blk = blockIdx.x & 63;
    scan_core5<SEQ, 2>(dir ? Whh_b : Whh_f, dir ? bhh_b : bhh_f,
                       dir ? g_gi_b : g_gi_f,
                       g_he[0][dir], g_he[1][dir],
                       nullptr, nullptr,
                       dir, blk * 8, dir, 64, g_enc_out);
}

// decoder: 64 blocks (8 i each), h0 = enc hf + hb
__global__ void __launch_bounds__(256, 1) dec_scan5(const float* __restrict__ Whh,
                                                    const float* __restrict__ bhh)
{
    scan_core5<TM1, 1>(Whh, bhh, g_gid,
                       g_hdd[0], g_hdd[1],
                       g_he[0][0], g_he[0][1],
                       0, blockIdx.x * 8, 2, 64, g_Hs);
}

// ---------------- attention: scores + softmax + ctx2h (once) ---------------
__global__ void attn_kernel(const int* __restrict__ amask) {
    int b = blockIdx.x, tid = threadIdx.x;
    __shared__ float vs[1024];
    __shared__ float ws[SEQ];
    __shared__ float red[16];
    for (int x = tid; x < 1024; x += 256) vs[x] = g_v[x];
    __syncthreads();

    const float* row = g_enc_out + ((size_t)b * SEQ + tid) * 1024;
    ull acc2 = 0ull;
    for (int k = 0; k < 1024; k += 4) {
        F4U e, v;
        e.f = *(const float4*)(row + k);
        v.f = *(const float4*)(vs + k);
        acc2 = fma2(e.u[0], v.u[0], acc2);
        acc2 = fma2(e.u[1], v.u[1], acc2);
    }
    float sc = hsum2(acc2) + g_c0;
    if (amask[b * SEQ + tid] == 0) sc = -1e9f;

    float m = sc;
    #pragma unroll
    for (int o = 16; o; o >>= 1) m = fmaxf(m, __shfl_xor_sync(0xffffffffu, m, o));
    if ((tid & 31) == 0) red[tid >> 5] = m;
    __syncthreads();
    if (tid < 32) {
        float t = (tid < 8) ? red[tid] : -3.4e38f;
        #pragma unroll
        for (int o = 4; o; o >>= 1) t = fmaxf(t, __shfl_xor_sync(0xffffffffu, t, o));
        if (tid == 0) red[0] = t;
    }
    __syncthreads();
    float mx = red[0];
    float e = expf(sc - mx);
    float sm = e;
    #pragma unroll
    for (int o = 16; o; o >>= 1) sm += __shfl_xor_sync(0xffffffffu, sm, o);
    __syncthreads();
    if ((tid & 31) == 0) red[8 + (tid >> 5)] = sm;
    __syncthreads();
    if (tid < 32) {
        float t = (tid < 8) ? red[8 + tid] : 0.f;
        #pragma unroll
        for (int o = 4; o; o >>= 1) t += __shfl_xor_sync(0xffffffffu, t, o);
        if (tid == 0) red[0] = t;
    }
    __syncthreads();
    float total = red[0];
    ws[tid] = e / total;
    __syncthreads();

    #pragma unroll
    for (int kk = 0; kk < 4; kk++) {
        int k = tid + kk * 256;
        float a2 = 0.f;
        for (int s = 0; s < SEQ; s++)
            a2 += ws[s] * g_enc_out[((size_t)b * SEQ + s) * 1024 + k];
        g_ctx2h[b * 1024 + k] = a2;
    }
}

// ---------------- small GEMMs: proj / ctx_gi / base ------------------------
__global__ void small_mm(const float* __restrict__ W, const float* __restrict__ bias,
                         int mode, int N, int K, int ldw, int koff) {
    int idx = blockIdx.x * 256 + threadIdx.x;
    if (idx >= 16 * N) return;
    int b = idx & 15, n = idx >> 4;
    const float* A = (mode == 0) ? (g_ctx2h + b * 1024) : (g_ctx + b * 512);
    const float* w = W + (size_t)n * ldw + koff;
    ull acc2 = 0ull;
    for (int k = 0; k < K; k += 4) {
        F4U av, wv;
        av.f = *(const float4*)(A + k);
        wv.f = *(const float4*)(w + k);
        acc2 = fma2(av.u[0], wv.u[0], acc2);
        acc2 = fma2(av.u[1], wv.u[1], acc2);
    }
    float acc = hsum2(acc2) + bias[n];
    if (mode == 0)      g_ctx[b * 512 + n] = acc;
    else if (mode == 1) g_ctxgi[b * 1536 + n] = acc;
    else                g_base[(size_t)b * VOC + n] = acc;
}

// ---------------- launch -------------------------------------------------
extern "C" void kernel_launch(void* const* d_in, const int* in_sizes, int n_in,
                              void* d_out, int out_size) {
    const float* bert   = (const float*)d_in[0];
    const int*   amask  = (const int*)d_in[1];
    const int*   ids    = (const int*)d_in[2];
    const float* emb    = (const float*)d_in[3];
    const float* eWih_f = (const float*)d_in[4];
    const float* eWhh_f = (const float*)d_in[5];
    const float* ebih_f = (const float*)d_in[6];
    const float* ebhh_f = (const float*)d_in[7];
    const float* eWih_b = (const float*)d_in[8];
    const float* eWhh_b = (const float*)d_in[9];
    const float* ebih_b = (const float*)d_in[10];
    const float* ebhh_b = (const float*)d_in[11];
    const float* dWih   = (const float*)d_in[12];
    const float* dWhh   = (const float*)d_in[13];
    const float* dbih   = (const float*)d_in[14];
    const float* dbhh   = (const float*)d_in[15];
    const float* attn_W = (const float*)d_in[16];
    const float* attn_b = (const float*)d_in[17];
    const float* comb_W = (const float*)d_in[18];
    const float* comb_b = (const float*)d_in[19];
    const float* proj_W = (const float*)d_in[20];
    const float* proj_b = (const float*)d_in[21];
    const float* out_W  = (const float*)d_in[22];
    const float* out_b  = (const float*)d_in[23];
    float* out = (float*)d_out;

    const int SGEMM_SMEM = 49152;

    static int attr_done = 0;
    if (!attr_done) {
        cudaFuncSetAttribute(sgemm2<0>, cudaFuncAttributeMaxDynamicSharedMemorySize, SGEMM_SMEM);
        cudaFuncSetAttribute(sgemm2<1>, cudaFuncAttributeMaxDynamicSharedMemorySize, SGEMM_SMEM);
        cudaFuncSetAttribute(sgemm2<2>, cudaFuncAttributeMaxDynamicSharedMemorySize, SGEMM_SMEM);
        cudaFuncSetAttribute(enc_scan5, cudaFuncAttributeMaxDynamicSharedMemorySize, SCAN5_SMEM);
        cudaFuncSetAttribute(dec_scan5, cudaFuncAttributeMaxDynamicSharedMemorySize, SCAN5_SMEM);
        attr_done = 1;
    }

    // attention folding + barrier reset
    fold_kernel<<<4, 256>>>(attn_W, attn_b, comb_W, comb_b);

    // encoder input gates
    sgemm2<0><<<dim3(12, 32), 256, SGEMM_SMEM>>>(bert, eWih_f, 768, ebih_f, nullptr, nullptr, 0, 4096, 1536, 768);
    sgemm2<0><<<dim3(12, 32), 256, SGEMM_SMEM>>>(bert, eWih_b, 768, ebih_b, nullptr, nullptr, 1, 4096, 1536, 768);

    // bidirectional encoder scan (persistent, 128 blocks, weight-reuse v5)
    enc_scan5<<<128, 256, SCAN5_SMEM>>>(eWhh_f, ebhh_f, eWhh_b, ebhh_b);

    // attention (once — h-dependence cancels in softmax)
    attn_kernel<<<16, 256>>>(amask);

    // ctx = ctx2h @ proj_W.T + proj_b ; ctx_gi = ctx @ dec_Wih[:,768:].T + dec_bih
    small_mm<<<32, 256>>>(proj_W, proj_b, 0, 512, 1024, 1024, 0);
    small_mm<<<96, 256>>>(dWih, dbih, 1, 1536, 512, 1280, 768);

    // decoder input gates
    sgemm2<1><<<dim3(12, 13), 256, SGEMM_SMEM>>>(emb, dWih, 1280, nullptr, ids, nullptr, 0, 1584, 1536, 768);

    // decoder scan (persistent, 64 blocks)
    dec_scan5<<<64, 256, SCAN5_SMEM>>>(dWhh, dbhh);

    // base = ctx @ out_W[:,512:].T + out_b
    small_mm<<<1908, 256>>>(out_W, out_b, 2, VOC, 512, 1024, 512);

    // logits = Hs @ out_W[:,:512].T + base
    sgemm2<2><<<dim3(239, 13), 256, SGEMM_SMEM>>>(nullptr, out_W, 1024, nullptr, nullptr, out, 0, 1584, VOC, 512);
}

// round 17
// speedup vs baseline: 3.3773x; 1.0348x over previous
#include <cuda_runtime.h>
#include <math.h>
#include <stdint.h>

typedef unsigned long long ull;
typedef unsigned int uint;

// Problem constants
#define SEQ   256
#define BSZ   16
#define HID   512
#define EMB   768
#define VOC   30522
#define TM1   99

// ---------------- scratch (device globals; no allocations) ----------------
__device__ float g_gi_f[SEQ*BSZ*1536];
__device__ float g_gi_b[SEQ*BSZ*1536];
__device__ float g_enc_out[BSZ*SEQ*1024];
__device__ float g_he[2][2][8192];     // encoder h double-buffer [parity][dir]
__device__ float g_hdd[2][8192];       // decoder h double-buffer [parity]
__device__ float g_v[1024];
__device__ float g_c0;
__device__ float g_ctx2h[BSZ*1024];
__device__ float g_ctx[BSZ*HID];
__device__ float g_ctxgi[BSZ*1536];
__device__ float g_gid[TM1*BSZ*1536];
__device__ float g_Hs[TM1*BSZ*HID];
__device__ float g_base[BSZ*VOC];
__device__ unsigned int g_cnt[4 * 32];
__device__ unsigned int g_flag[4 * 32];

// ---------------- f32x2 helpers -------------------------------------------
__device__ __forceinline__ ull fma2(ull a, ull b, ull c) {
    ull d;
    asm("fma.rn.f32x2 %0, %1, %2, %3;" : "=l"(d) : "l"(a), "l"(b), "l"(c));
    return d;
}
__device__ __forceinline__ ull add2(ull a, ull b) {
    ull d;
    asm("add.rn.f32x2 %0, %1, %2;" : "=l"(d) : "l"(a), "l"(b));
    return d;
}
__device__ __forceinline__ ull dup2(float x) {
    ull d;
    asm("mov.b64 %0, {%1, %1};" : "=l"(d) : "f"(x));
    return d;
}
__device__ __forceinline__ float hsum2(ull v) {
    float x, y;
    asm("mov.b64 {%0, %1}, %2;" : "=f"(x), "=f"(y) : "l"(v));
    return x + y;
}
__device__ __forceinline__ float2 unp2(ull v) {
    float2 r;
    asm("mov.b64 {%0, %1}, %2;" : "=f"(r.x), "=f"(r.y) : "l"(v));
    return r;
}
union F4U { float4 f; ull u[2]; };

__device__ __forceinline__ float sigmoidf_(float x) { return 1.0f / (1.0f + expf(-x)); }

// ---------------- grid barrier (split count/flag, release-RMW) -------------
__device__ __forceinline__ void gbar2(int id, unsigned nb, unsigned tgt) {
    __syncthreads();
    if (threadIdx.x == 0) {
        unsigned v;
        asm volatile("atom.release.gpu.add.u32 %0, [%1], %2;"
                     : "=r"(v) : "l"(&g_cnt[id * 32]), "r"(1u) : "memory");
        v += 1u;
        if (v == nb * tgt) {
            asm volatile("st.release.gpu.u32 [%0], %1;"
                         :: "l"(&g_flag[id * 32]), "r"(tgt) : "memory");
        } else {
            unsigned f;
            do {
                asm volatile("ld.acquire.gpu.u32 %0, [%1];"
                             : "=r"(f) : "l"(&g_flag[id * 32]) : "memory");
            } while (f < tgt);
        }
    }
    __syncthreads();
}

// ---------------- fold attention + barrier reset ---------------------------
__global__ void fold_kernel(const float* __restrict__ attn_W, const float* __restrict__ attn_b,
                            const float* __restrict__ comb_W, const float* __restrict__ comb_b) {
    if (blockIdx.x == 0 && threadIdx.x < 4) {
        g_cnt[threadIdx.x * 32] = 0u;
        g_flag[threadIdx.x * 32] = 0u;
    }
    int k = blockIdx.x * 256 + threadIdx.x;
    if (k < 1024) {
        float acc = 0.f;
        for (int j = 0; j < 512; j++) acc += comb_W[j] * attn_W[(size_t)j * 1536 + k];
        g_v[k] = acc;
    }
    if (blockIdx.x == 0 && threadIdx.x == 0) {
        float c = comb_b[0];
        for (int j = 0; j < 512; j++) c += comb_W[j] * attn_b[j];
        g_c0 = c;
    }
}

// ---------------- SGEMM tile body (device fn; bx/by explicit) --------------
// MODE 0: C -> g_gi_f / g_gi_b (sel), + bias[n]
// MODE 1: A rows gathered from emb, C -> g_gid RAW (ctxgi added later)
// MODE 2: A = g_Hs, C -> out[(b*99+t)*VOC + n], + g_base[b][n]
template<int MODE>
__device__ __forceinline__ void sgemm_tile(
    const float* __restrict__ Asrc, const float* __restrict__ W, int ldw,
    const float* __restrict__ bias, const int* __restrict__ toks,
    float* __restrict__ Cout, int sel, int M, int N, int K, int rowbase,
    int bx, int by)
{
    const int BM = 128, BN = 128, BK = 32;
    extern __shared__ char smraw[];
    float* As = (float*)smraw;
    ull*   Bs = (ull*)(smraw + BK * BM * 4);

    int tid = threadIdx.x;
    int row0 = rowbase + by * BM, col0 = bx * BN;
    int tx = tid & 15, ty = tid >> 4;

    int a_m  = tid >> 1;
    int a_kq = (tid & 1) * 16;
    int am = row0 + a_m;
    const float* Ap = nullptr;
    if (am < M) {
        if (MODE == 0) {
            int s = am >> 4, b = am & 15;
            Ap = Asrc + ((size_t)b * SEQ + s) * EMB;
        } else if (MODE == 1) {
            int t = am >> 4, b = am & 15;
            Ap = Asrc + (size_t)toks[b * 100 + t] * EMB;
        } else {
            Ap = g_Hs + (size_t)am * HID;
        }
    }
    int b_n  = tid >> 1;
    int b_kq = (tid & 1) * 16;
    int wn = col0 + b_n;
    const float* Wp = (wn < N) ? (W + (size_t)wn * ldw) : nullptr;

    ull acc[4][8];
    #pragma unroll
    for (int ip = 0; ip < 4; ip++)
        #pragma unroll
        for (int j = 0; j < 8; j++) acc[ip][j] = 0ull;

    float4 rA[4], rB[4];
    #pragma unroll
    for (int q = 0; q < 4; q++) {
        rA[q] = Ap ? *(const float4*)(Ap + a_kq + q * 4) : make_float4(0.f, 0.f, 0.f, 0.f);
        rB[q] = Wp ? *(const float4*)(Wp + b_kq + q * 4) : make_float4(0.f, 0.f, 0.f, 0.f);
    }

    int T = K / BK;
    for (int t = 0; t < T; t++) {
        __syncthreads();
        #pragma unroll
        for (int q = 0; q < 4; q++) {
            int ka = a_kq + q * 4;
            As[(ka + 0) * BM + a_m] = rA[q].x;
            As[(ka + 1) * BM + a_m] = rA[q].y;
            As[(ka + 2) * BM + a_m] = rA[q].z;
            As[(ka + 3) * BM + a_m] = rA[q].w;
            int kb = b_kq + q * 4;
            Bs[(kb + 0) * BN + b_n] = dup2(rB[q].x);
            Bs[(kb + 1) * BN + b_n] = dup2(rB[q].y);
            Bs[(kb + 2) * BN + b_n] = dup2(rB[q].z);
            Bs[(kb + 3) * BN + b_n] = dup2(rB[q].w);
        }
        __syncthreads();
        if (t + 1 < T) {
            int k0 = (t + 1) * BK;
            #pragma unroll
            for (int q = 0; q < 4; q++) {
                rA[q] = Ap ? *(const float4*)(Ap + k0 + a_kq + q * 4) : make_float4(0.f, 0.f, 0.f, 0.f);
                rB[q] = Wp ? *(const float4*)(Wp + k0 + b_kq + q * 4) : make_float4(0.f, 0.f, 0.f, 0.f);
            }
        }
        #pragma unroll 8
        for (int kk = 0; kk < BK; kk++) {
            F4U a0, a1;
            a0.f = *(const float4*)&As[kk * BM + ty * 8];
            a1.f = *(const float4*)&As[kk * BM + ty * 8 + 4];
            ull ap[4] = {a0.u[0], a0.u[1], a1.u[0], a1.u[1]};
            const ull* bp = Bs + kk * BN + tx * 8;
            ulonglong2 q0 = *(const ulonglong2*)(bp);
            ulonglong2 q1 = *(const ulonglong2*)(bp + 2);
            ulonglong2 q2 = *(const ulonglong2*)(bp + 4);
            ulonglong2 q3 = *(const ulonglong2*)(bp + 6);
            ull bb[8] = {q0.x, q0.y, q1.x, q1.y, q2.x, q2.y, q3.x, q3.y};
            #pragma unroll
            for (int ip = 0; ip < 4; ip++)
                #pragma unroll
                for (int j = 0; j < 8; j++)
                    acc[ip][j] = fma2(ap[ip], bb[j], acc[ip][j]);
        }
    }

    #pragma unroll
    for (int ip = 0; ip < 4; ip++) {
        int m0 = row0 + ty * 8 + ip * 2;
        #pragma unroll
        for (int j = 0; j < 8; j++) {
            int n = col0 + tx * 8 + j;
            if (n >= N) continue;
            float2 v = unp2(acc[ip][j]);
            #pragma unroll
            for (int h = 0; h < 2; h++) {
                int m = m0 + h;
                if (m >= M) continue;
                float val = (h == 0) ? v.x : v.y;
                int b = m & 15, t = m >> 4;
                if (MODE == 0) {
                    val += bias[n];
                    float* dst = sel ? g_gi_b : g_gi_f;
                    dst[(size_t)m * 1536 + n] = val;
                } else if (MODE == 1) {
                    g_gid[(size_t)m * 1536 + n] = val;   // raw; ctxgi added later
                } else {
                    val += g_base[(size_t)b * VOC + n];
                    Cout[((size_t)b * TM1 + t) * VOC + n] = val;
                }
            }
        }
    }
}

template<int MODE>
__global__ void __launch_bounds__(256) sgemm2(
    const float* __restrict__ Asrc, const float* __restrict__ W, int ldw,
    const float* __restrict__ bias, const int* __restrict__ toks,
    float* __restrict__ Cout, int sel, int M, int N, int K, int rowbase)
{
    sgemm_tile<MODE>(Asrc, W, ldw, bias, toks, Cout, sel, M, N, K, rowbase,
                     blockIdx.x, blockIdx.y);
}

// ---------------- g_gid += ctxgi (broadcast over t) ------------------------
__global__ void add_ctxgi() {
    int idx = blockIdx.x * 256 + threadIdx.x;    // float4 index
    if (idx >= TM1 * BSZ * 1536 / 4) return;
    int e = idx * 4;
    int row = e / 1536;
    int col = e - row * 1536;
    int b = row & 15;
    float4 g = *(float4*)(g_gid + e);
    float4 c = *(const float4*)(g_ctxgi + b * 1536 + col);
    g.x += c.x; g.y += c.y; g.z += c.z; g.w += c.w;
    *(float4*)(g_gid + e) = g;
}

// ---------------- persistent GRU scan core ---------------------------------
struct ScanSmem {
    float Wsm[12 * 512];
    float hs[8192];
    float red[12 * 2 * 16];
};

template<int DIRS>
__device__ __forceinline__ void scan_core(
    const float* __restrict__ Whh, const float* __restrict__ bhh,
    const float* __restrict__ gi,
    float* __restrict__ buf0, float* __restrict__ buf1,
    const float* __restrict__ init_a, const float* __restrict__ init_b,
    int dir, int i0, int bar_id, unsigned nb,
    float* __restrict__ extra_out, int step0, int nsteps)
{
    extern __shared__ char smraw[];
    ScanSmem* S = (ScanSmem*)smraw;

    int tid = threadIdx.x;
    int warp = tid >> 5, lane = tid & 31;
    int i_local = warp & 3, ks_hi = warp >> 2;
    int b = lane & 15, ks_lo = lane >> 4;
    int k0 = (ks_hi * 2 + ks_lo) * 128;

    for (int x = tid; x < 1536; x += 256) {
        int r = x >> 7;
        int c = (x & 127) * 4;
        int g = r >> 2, i_l = r & 3;
        *(float4*)(S->Wsm + r * 512 + c) =
            __ldg((const float4*)(Whh + ((size_t)(g * 512) + i0 + i_l) * 512 + c));
    }
    if (init_a == nullptr) {
        for (int x = tid; x < 2048; x += 256)
            ((float4*)S->hs)[x] = make_float4(0.f, 0.f, 0.f, 0.f);
    } else if (init_b == nullptr) {
        for (int x = tid; x < 2048; x += 256)
            ((float4*)S->hs)[x] = __ldcg(((const float4*)init_a) + x);
    } else {
        for (int x = tid; x < 2048; x += 256) {
            float4 a = __ldcg(((const float4*)init_a) + x);
            float4 c = __ldcg(((const float4*)init_b) + x);
            ((float4*)S->hs)[x] = make_float4(a.x + c.x, a.y + c.y, a.z + c.z, a.w + c.w);
        }
    }
    __syncthreads();

    const float* wr = S->Wsm + (0 * 4 + i_local) * 512 + k0;
    const float* wz = S->Wsm + (1 * 4 + i_local) * 512 + k0;
    const float* wn = S->Wsm + (2 * 4 + i_local) * 512 + k0;
    const float* hbase = S->hs + (k0 >> 2) * 64 + b * 4;

    int b2 = tid & 15, il2 = (tid >> 4) & 3;
    int i = i0 + il2;
    float bh_r = bhh[i], bh_z = bhh[i + 512], bh_n = bhh[i + 1024];
    int hidx = (i >> 2) * 64 + b2 * 4 + (i & 3);

    for (int step = 0; step < nsteps; step++) {
        int t_abs = step0 + step;
        int s = (DIRS == 2 && dir) ? (SEQ - 1 - t_abs) : t_abs;
        float* wbuf = (t_abs & 1) ? buf0 : buf1;

        float gv0 = 0.f, gv1 = 0.f, gv2 = 0.f;
        if (tid < 64) {
            const float* gp = gi + ((size_t)s * 16 + b2) * 1536 + i;
            gv0 = __ldg(gp);
            gv1 = __ldg(gp + 512);
            gv2 = __ldg(gp + 1024);
        }

        ull pr = 0ull, pz = 0ull, pn = 0ull;
        #pragma unroll 8
        for (int kq = 0; kq < 32; kq++) {
            F4U h4; h4.f = *(const float4*)(hbase + kq * 64);
            F4U w;
            w.f = *(const float4*)(wr + kq * 4);
            pr = fma2(w.u[0], h4.u[0], pr); pr = fma2(w.u[1], h4.u[1], pr);
            w.f = *(const float4*)(wz + kq * 4);
            pz = fma2(w.u[0], h4.u[0], pz); pz = fma2(w.u[1], h4.u[1], pz);
            w.f = *(const float4*)(wn + kq * 4);
            pn = fma2(w.u[0], h4.u[0], pn); pn = fma2(w.u[1], h4.u[1], pn);
        }
        pr = add2(pr, __shfl_xor_sync(0xffffffffu, pr, 16));
        pz = add2(pz, __shfl_xor_sync(0xffffffffu, pz, 16));
        pn = add2(pn, __shfl_xor_sync(0xffffffffu, pn, 16));
        if (ks_lo == 0) {
            S->red[(0 * 4 + i_local) * 32 + ks_hi * 16 + b] = hsum2(pr);
            S->red[(1 * 4 + i_local) * 32 + ks_hi * 16 + b] = hsum2(pz);
            S->red[(2 * 4 + i_local) * 32 + ks_hi * 16 + b] = hsum2(pn);
        }
        __syncthreads();

        if (tid < 64) {
            float dr = S->red[(0 * 4 + il2) * 32 + b2] + S->red[(0 * 4 + il2) * 32 + 16 + b2];
            float dz = S->red[(1 * 4 + il2) * 32 + b2] + S->red[(1 * 4 + il2) * 32 + 16 + b2];
            float dn = S->red[(2 * 4 + il2) * 32 + b2] + S->red[(2 * 4 + il2) * 32 + 16 + b2];
            float r = sigmoidf_(gv0 + dr + bh_r);
            float z = sigmoidf_(gv1 + dz + bh_z);
            float n = tanhf(gv2 + r * (dn + bh_n));
            float hnew = (1.f - z) * n + z * S->hs[hidx];
            wbuf[hidx] = hnew;
            if (DIRS == 2)
                extra_out[((size_t)b2 * SEQ + s) * 1024 + dir * 512 + i] = hnew;
            else
                extra_out[((size_t)s * 16 + b2) * 512 + i] = hnew;
        }

        if (step + 1 < nsteps) {
            gbar2(bar_id, nb, (unsigned)(step + 1));
            for (int x = tid; x < 2048; x += 256)
                ((float4*)S->hs)[x] = __ldcg(((const float4*)wbuf) + x);
            __syncthreads();
        }
    }
}

// ---------------- hybrid A: enc scan (blocks 0-255) + dec-gi GEMM ----------
__global__ void __launch_bounds__(256, 2) hybridA(
    const float* __restrict__ Whh_f, const float* __restrict__ bhh_f,
    const float* __restrict__ Whh_b, const float* __restrict__ bhh_b,
    const float* __restrict__ emb, const int* __restrict__ ids,
    const float* __restrict__ dWih)
{
    int bid = blockIdx.x;
    if (bid < 256) {
        int dir = bid >> 7;
        int blk = bid & 127;
        scan_core<2>(dir ? Whh_b : Whh_f, dir ? bhh_b : bhh_f,
                     dir ? g_gi_b : g_gi_f,
                     g_he[0][dir], g_he[1][dir],
                     nullptr, nullptr,
                     dir, blk * 4, dir, 128, g_enc_out, 0, SEQ);
    } else {
        int e = bid - 256;          // 0..155, dec-gi grid (12 x 13)
        int bx = e % 12, by = e / 12;
        sgemm_tile<1>(emb, dWih, 1280, nullptr, ids, nullptr, 0,
                      1584, 1536, 768, 0, bx, by);
    }
}

// ---------------- dec scan segment 1 (t=0..48, barrier 2) ------------------
__global__ void __launch_bounds__(256, 2) dec_seg1(
    const float* __restrict__ Whh, const float* __restrict__ bhh)
{
    scan_core<1>(Whh, bhh, g_gid,
                 g_hdd[0], g_hdd[1],
                 g_he[0][0], g_he[0][1],
                 0, blockIdx.x * 4, 2, 128, g_Hs, 0, 49);
}

// ---------------- hybrid B: dec scan seg2 (blocks 0-127) + logits p1 -------
__global__ void __launch_bounds__(256, 2) hybridB(
    const float* __restrict__ Whh, const float* __restrict__ bhh,
    const float* __restrict__ out_W, float* __restrict__ out)
{
    int bid = blockIdx.x;
    if (bid < 128) {
        scan_core<1>(Whh, bhh, g_gid,
                     g_hdd[0], g_hdd[1],
                     g_hdd[1], nullptr,
                     0, bid * 4, 3, 128, g_Hs, 49, 50);
    } else {
        int e = bid - 128;          // 0..1672, logits p1 grid (239 x 7)
        int bx = e % 239, by = e / 239;
        sgemm_tile<2>(nullptr, out_W, 1024, nullptr, nullptr, out, 0,
                      784, VOC, 512, 0, bx, by);
    }
}

// ---------------- attention: scores + softmax + ctx2h (once) ---------------
__global__ void attn_kernel(const int* __restrict__ amask) {
    int b = blockIdx.x, tid = threadIdx.x;
    __shared__ float vs[1024];
    __shared__ float ws[SEQ];
    __shared__ float red[16];
    for (int x = tid; x < 1024; x += 256) vs[x] = g_v[x];
    __syncthreads();

    const float* row = g_enc_out + ((size_t)b * SEQ + tid) * 1024;
    ull acc2 = 0ull;
    for (int k = 0; k < 1024; k += 4) {
        F4U e, v;
        e.f = *(const float4*)(row + k);
        v.f = *(const float4*)(vs + k);
        acc2 = fma2(e.u[0], v.u[0], acc2);
        acc2 = fma2(e.u[1], v.u[1], acc2);
    }
    float sc = hsum2(acc2) + g_c0;
    if (amask[b * SEQ + tid] == 0) sc = -1e9f;

    float m = sc;
    #pragma unroll
    for (int o = 16; o; o >>= 1) m = fmaxf(m, __shfl_xor_sync(0xffffffffu, m, o));
    if ((tid & 31) == 0) red[tid >> 5] = m;
    __syncthreads();
    if (tid < 32) {
        float t = (tid < 8) ? red[tid] : -3.4e38f;
        #pragma unroll
        for (int o = 4; o; o >>= 1) t = fmaxf(t, __shfl_xor_sync(0xffffffffu, t, o));
        if (tid == 0) red[0] = t;
    }
    __syncthreads();
    float mx = red[0];
    float e = expf(sc - mx);
    float sm = e;
    #pragma unroll
    for (int o = 16; o; o >>= 1) sm += __shfl_xor_sync(0xffffffffu, sm, o);
    __syncthreads();
    if ((tid & 31) == 0) red[8 + (tid >> 5)] = sm;
    __syncthreads();
    if (tid < 32) {
        float t = (tid < 8) ? red[8 + tid] : 0.f;
        #pragma unroll
        for (int o = 4; o; o >>= 1) t += __shfl_xor_sync(0xffffffffu, t, o);
        if (tid == 0) red[0] = t;
    }
    __syncthreads();
    float total = red[0];
    ws[tid] = e / total;
    __syncthreads();

    #pragma unroll
    for (int kk = 0; kk < 4; kk++) {
        int k = tid + kk * 256;
        float a2 = 0.f;
        for (int s = 0; s < SEQ; s++)
            a2 += ws[s] * g_enc_out[((size_t)b * SEQ + s) * 1024 + k];
        g_ctx2h[b * 1024 + k] = a2;
    }
}

// ---------------- small GEMMs: proj / ctx_gi / base ------------------------
__global__ void small_mm(const float* __restrict__ W, const float* __restrict__ bias,
                         int mode, int N, int K, int ldw, int koff) {
    int idx = blockIdx.x * 256 + threadIdx.x;
    if (idx >= 16 * N) return;
    int b = idx & 15, n = idx >> 4;
    const float* A = (mode == 0) ? (g_ctx2h + b * 1024) : (g_ctx + b * 512);
    const float* w = W + (size_t)n * ldw + koff;
    ull acc2 = 0ull;
    for (int k = 0; k < K; k += 4) {
        F4U av, wv;
        av.f = *(const float4*)(A + k);
        wv.f = *(const float4*)(w + k);
        acc2 = fma2(av.u[0], wv.u[0], acc2);
        acc2 = fma2(av.u[1], wv.u[1], acc2);
    }
    float acc = hsum2(acc2) + bias[n];
    if (mode == 0)      g_ctx[b * 512 + n] = acc;
    else if (mode == 1) g_ctxgi[b * 1536 + n] = acc;
    else                g_base[(size_t)b * VOC + n] = acc;
}

// ---------------- launch -------------------------------------------------
extern "C" void kernel_launch(void* const* d_in, const int* in_sizes, int n_in,
                              void* d_out, int out_size) {
    const float* bert   = (const float*)d_in[0];
    const int*   amask  = (const int*)d_in[1];
    const int*   ids    = (const int*)d_in[2];
    const float* emb    = (const float*)d_in[3];
    const float* eWih_f = (const float*)d_in[4];
    const float* eWhh_f = (const float*)d_in[5];
    const float* ebih_f = (const float*)d_in[6];
    const float* ebhh_f = (const float*)d_in[7];
    const float* eWih_b = (const float*)d_in[8];
    const float* eWhh_b = (const float*)d_in[9];
    const float* ebih_b = (const float*)d_in[10];
    const float* ebhh_b = (const float*)d_in[11];
    const float* dWih   = (const float*)d_in[12];
    const float* dWhh   = (const float*)d_in[13];
    const float* dbih   = (const float*)d_in[14];
    const float* dbhh   = (const float*)d_in[15];
    const float* attn_W = (const float*)d_in[16];
    const float* attn_b = (const float*)d_in[17];
    const float* comb_W = (const float*)d_in[18];
    const float* comb_b = (const float*)d_in[19];
    const float* proj_W = (const float*)d_in[20];
    const float* proj_b = (const float*)d_in[21];
    const float* out_W  = (const float*)d_in[22];
    const float* out_b  = (const float*)d_in[23];
    float* out = (float*)d_out;

    const int SGEMM_SMEM = 49152;
    const int SCAN_SMEM  = (int)sizeof(ScanSmem);

    static int attr_done = 0;
    if (!attr_done) {
        cudaFuncSetAttribute(sgemm2<0>, cudaFuncAttributeMaxDynamicSharedMemorySize, SGEMM_SMEM);
        cudaFuncSetAttribute(sgemm2<2>, cudaFuncAttributeMaxDynamicSharedMemorySize, SGEMM_SMEM);
        cudaFuncSetAttribute(hybridA,  cudaFuncAttributeMaxDynamicSharedMemorySize, SCAN_SMEM);
        cudaFuncSetAttribute(hybridB,  cudaFuncAttributeMaxDynamicSharedMemorySize, SCAN_SMEM);
        cudaFuncSetAttribute(dec_seg1, cudaFuncAttributeMaxDynamicSharedMemorySize, SCAN_SMEM);
        attr_done = 1;
    }

    // attention folding + barrier reset
    fold_kernel<<<4, 256>>>(attn_W, attn_b, comb_W, comb_b);

    // encoder input gates
    sgemm2<0><<<dim3(12, 32), 256, SGEMM_SMEM>>>(bert, eWih_f, 768, ebih_f, nullptr, nullptr, 0, 4096, 1536, 768, 0);
    sgemm2<0><<<dim3(12, 32), 256, SGEMM_SMEM>>>(bert, eWih_b, 768, ebih_b, nullptr, nullptr, 1, 4096, 1536, 768, 0);

    // hybrid A: encoder scan (blocks 0-255) + decoder-gi GEMM (blocks 256-411)
    hybridA<<<412, 256, SCAN_SMEM>>>(eWhh_f, ebhh_f, eWhh_b, ebhh_b, emb, ids, dWih);

    // attention (once), ctx, ctxgi
    attn_kernel<<<16, 256>>>(amask);
    small_mm<<<32, 256>>>(proj_W, proj_b, 0, 512, 1024, 1024, 0);
    small_mm<<<96, 256>>>(dWih, dbih, 1, 1536, 512, 1280, 768);

    // g_gid += ctxgi broadcast
    add_ctxgi<<<(TM1 * BSZ * 1536 / 4 + 255) / 256, 256>>>();

    // base = ctx @ out_W[:,512:].T + out_b
    small_mm<<<1908, 256>>>(out_W, out_b, 2, VOC, 512, 1024, 512);

    // decoder scan segment 1: t = 0..48
    dec_seg1<<<128, 256, SCAN_SMEM>>>(dWhh, dbhh);

    // hybrid B: decoder scan seg2 (blocks 0-127) + logits rows<784 (blocks 128-1800)
    hybridB<<<1801, 256, SCAN_SMEM>>>(dWhh, dbhh, out_W, out);

    // logits rows 784..1583
    sgemm2<2><<<dim3(239, 7), 256, SGEMM_SMEM>>>(nullptr, out_W, 1024, nullptr, nullptr,
                                                 out, 0, 1584, VOC, 512, 784);
}